// round 12
// baseline (speedup 1.0000x reference)
#include <cuda_runtime.h>
#include <cuda_bf16.h>
#include <math.h>
#include <cstdint>

#define WINS 4
#define LTOK 36
#define DHD  8

// Weights, mma-B-fragment interleaved: [win][chunk4][tap9][hl2][co64][16] bf16
__device__ __align__(16) __nv_bfloat16 g_wB[4 * 4 * 9 * 2 * 64 * 16];
// X converted: [hl][b][wx2][chunk4][gy256][px132][ci16] bf16 (px slot 0 and 129+ zero)
__device__ __align__(16) __nv_bfloat16 g_xbf[2ULL * 8 * 2 * 4 * 256 * 132 * 16];

// hl=1 offset in uint4 units
#define XLO_U4 4325376ULL

__device__ __forceinline__ uint32_t smem_u32(const void* p) {
    uint32_t a;
    asm("{ .reg .u64 t; cvta.to.shared.u64 t, %1; cvt.u32.u64 %0, t; }" : "=r"(a) : "l"(p));
    return a;
}

__device__ __forceinline__ void ldmx4(uint32_t* r, uint32_t addr) {
    asm volatile("ldmatrix.sync.aligned.m8n8.x4.shared.b16 {%0,%1,%2,%3}, [%4];"
        : "=r"(r[0]), "=r"(r[1]), "=r"(r[2]), "=r"(r[3]) : "r"(addr));
}

__device__ __forceinline__ void mma16816(float* d, const uint32_t* a, uint2 b) {
    asm volatile("mma.sync.aligned.m16n8k16.row.col.f32.bf16.bf16.f32 "
        "{%0,%1,%2,%3}, {%4,%5,%6,%7}, {%8,%9}, {%0,%1,%2,%3};"
        : "+f"(d[0]), "+f"(d[1]), "+f"(d[2]), "+f"(d[3])
        : "r"(a[0]), "r"(a[1]), "r"(a[2]), "r"(a[3]), "r"(b.x), "r"(b.y));
}

#define CP_ASYNC16(dst, src, sz) \
    asm volatile("cp.async.cg.shared.global [%0], [%1], 16, %2;" \
        :: "r"(dst), "l"(src), "r"(sz) : "memory")
#define CP_COMMIT() asm volatile("cp.async.commit_group;" ::: "memory")
#define CP_WAIT(n)  asm volatile("cp.async.wait_group %0;" :: "n"(n) : "memory")

// ===========================================================================
// Kernel PG: fused prep_x (blocks 0..16383) + gen_kernels (blocks 16384..16447)
// 288 threads.
// ===========================================================================
__global__ void __launch_bounds__(288) prep_gen(
    const float* __restrict__ x,
    const float* __restrict__ conv_w, const float* __restrict__ w_qkv,
    const float* __restrict__ b_qkv,  const float* __restrict__ w_out,
    const float* __restrict__ b_out,  const float* __restrict__ se_w1,
    const float* __restrict__ se_b1,  const float* __restrict__ se_w2,
    const float* __restrict__ se_b2)
{
    __shared__ float sm_a[LTOK * 64];
    __shared__ float sm_qkv[LTOK * 192];
    __shared__ float sm_k1[LTOK * 64];
    __shared__ float sm_pooled[64];
    __shared__ float sm_h1[4];

    const int t = threadIdx.x;

    if (blockIdx.x < 16384) {
        // -------------------- prep_x branch --------------------
        if (t >= 132) return;
        const int s  = blockIdx.x;
        const int gy = s & 255;
        const int yc = (s >> 8) & 7;
        const int wx = yc >> 2, c = yc & 3;
        const int b  = s >> 11;
        const int px = t;

        const bool in = (px >= 1 && px <= 128);
        const float* xp = x + (((size_t)(b * 64 + c * 16)) * 256 + gy) * 256
                            + wx * 128 + px - 1;
        float v[16];
#pragma unroll
        for (int ci = 0; ci < 16; ci++)
            v[ci] = in ? xp[(size_t)ci * 65536] : 0.f;

        uint32_t hw[8], lw[8];
#pragma unroll
        for (int j = 0; j < 8; j++) {
            float a = v[2 * j], bb = v[2 * j + 1];
            __nv_bfloat16 ha = __float2bfloat16(a);
            __nv_bfloat16 hb = __float2bfloat16(bb);
            __nv_bfloat16 la = __float2bfloat16(a - __bfloat162float(ha));
            __nv_bfloat16 lb = __float2bfloat16(bb - __bfloat162float(hb));
            hw[j] = (uint32_t)__bfloat16_as_ushort(ha) | ((uint32_t)__bfloat16_as_ushort(hb) << 16);
            lw[j] = (uint32_t)__bfloat16_as_ushort(la) | ((uint32_t)__bfloat16_as_ushort(lb) << 16);
        }
        const size_t slot = ((((size_t)b * 2 + wx) * 4 + c) * 256 + gy) * 132 + px;
        uint4* dh = (uint4*)g_xbf + slot * 2;
        uint4* dl = dh + XLO_U4;
        dh[0] = make_uint4(hw[0], hw[1], hw[2], hw[3]);
        dh[1] = make_uint4(hw[4], hw[5], hw[6], hw[7]);
        dl[0] = make_uint4(lw[0], lw[1], lw[2], lw[3]);
        dl[1] = make_uint4(lw[4], lw[5], lw[6], lw[7]);
        return;
    }

    // -------------------- gen_kernels branch --------------------
    const int o = blockIdx.x - 16384;

    for (int idx = t; idx < LTOK * 64; idx += 288) {
        int l = idx >> 6, i = idx & 63;
        int w_ = l / 9, p = l - w_ * 9;
        sm_a[idx] = conv_w[(((w_ * 64 + o) * 64 + i) * 9) + p];
    }
    __syncthreads();

    if (t < 192) {
        float wrow[64];
#pragma unroll
        for (int i = 0; i < 64; i++) wrow[i] = w_qkv[t * 64 + i];
        const float bj = b_qkv[t];
        for (int l = 0; l < LTOK; l++) {
            float acc = bj;
#pragma unroll
            for (int i = 0; i < 64; i++) acc += sm_a[l * 64 + i] * wrow[i];
            sm_qkv[l * 192 + t] = acc;
        }
    }
    __syncthreads();

    {
        const int h = t / LTOK;
        const int l = t - h * LTOK;
        const float scale = 0.3535533905932738f;
        float sc[LTOK];
        float mx = -1e30f;
#pragma unroll
        for (int m = 0; m < LTOK; m++) {
            float s_ = 0.f;
#pragma unroll
            for (int d = 0; d < DHD; d++)
                s_ += sm_qkv[l * 192 + h * 8 + d] * sm_qkv[m * 192 + 64 + h * 8 + d];
            sc[m] = s_ * scale;
            mx = fmaxf(mx, sc[m]);
        }
        float denom = 0.f;
#pragma unroll
        for (int m = 0; m < LTOK; m++) { sc[m] = expf(sc[m] - mx); denom += sc[m]; }
        const float inv = 1.f / denom;
        float ov[DHD];
#pragma unroll
        for (int d = 0; d < DHD; d++) ov[d] = 0.f;
#pragma unroll
        for (int m = 0; m < LTOK; m++) {
            const float p_ = sc[m];
#pragma unroll
            for (int d = 0; d < DHD; d++)
                ov[d] += p_ * sm_qkv[m * 192 + 128 + h * 8 + d];
        }
#pragma unroll
        for (int d = 0; d < DHD; d++)
            sm_a[l * 64 + h * 8 + d] = ov[d] * inv;
    }
    __syncthreads();

    if (t < 64) {
        const float bj = b_out[t];
        for (int l = 0; l < LTOK; l++) {
            float acc = bj;
#pragma unroll
            for (int c = 0; c < 64; c++) acc += sm_a[l * 64 + c] * w_out[t * 64 + c];
            sm_k1[l * 64 + t] = acc;
        }
    }
    __syncthreads();

    for (int w_ = 0; w_ < WINS; w_++) {
        if (t < 64) {
            float pl = 0.f;
#pragma unroll
            for (int p = 0; p < 9; p++) pl += sm_k1[(w_ * 9 + p) * 64 + t];
            sm_pooled[t] = pl * (1.f / 9.f);
        }
        __syncthreads();
        if (t < 4) {
            float a = se_b1[w_ * 4 + t];
            for (int i = 0; i < 64; i++)
                a += sm_pooled[i] * se_w1[(w_ * 4 + t) * 64 + i];
            sm_h1[t] = fmaxf(a, 0.f);
        }
        __syncthreads();
        if (t < 64) {   // t = ci (global)
            float z = se_b2[w_ * 64 + t];
#pragma unroll
            for (int r = 0; r < 4; r++) z += sm_h1[r] * se_w2[(w_ * 64 + t) * 4 + r];
            const float s_ = 1.f / (1.f + expf(-z));
            const int chunk = t >> 4, k = t & 15;
            const int j = (k & 7) >> 1;
            const int pos = 4 * j + (k & 1) + ((k >> 3) << 1);
#pragma unroll
            for (int p = 0; p < 9; p++) {
                float vv = sm_k1[(w_ * 9 + p) * 64 + t] * s_;
                __nv_bfloat16 h = __float2bfloat16(vv);
                __nv_bfloat16 l = __float2bfloat16(vv - __bfloat162float(h));
                size_t base = ((size_t)((w_ * 4 + chunk) * 9 + p) * 2) * 1024
                              + (size_t)o * 16 + pos;
                g_wB[base] = h;           // hl = 0
                g_wB[base + 1024] = l;    // hl = 1
            }
        }
        __syncthreads();
    }
}

// ===========================================================================
// Kernel B: mma.sync implicit-GEMM conv + LN + residual.
// cp.async double-buffered X staging; B fragments loaded once per (tap, nt).
// ===========================================================================
#define BUF_B 33792

__global__ void __launch_bounds__(256, 2) conv_ln(
    const float* __restrict__ x,
    const float* __restrict__ ln_w,
    const float* __restrict__ ln_b,
    float* __restrict__ out)
{
    extern __shared__ __align__(16) char smem[];   // 2 x 33792
    __shared__ float lnw[64], lnb[64];

    const int b  = blockIdx.z;
    const int w_ = blockIdx.y;
    const int wy = w_ >> 1, wx = w_ & 1;
    const int y0 = blockIdx.x << 1;
    const int t  = threadIdx.x;
    const int wid = t >> 5, lane = t & 31;
    const int r  = wid >> 2, qt = wid & 3;

    if (t < 64) { lnw[t] = ln_w[t]; lnb[t] = ln_b[t]; }

    float acc[2][8][4];
#pragma unroll
    for (int mt = 0; mt < 2; mt++)
#pragma unroll
        for (int nt = 0; nt < 8; nt++)
#pragma unroll
            for (int i = 0; i < 4; i++) acc[mt][nt][i] = 0.f;

    const uint32_t sx = smem_u32(smem);
    const int lane16 = lane & 15, lhalf = lane >> 4;

    // per-thread staging decode (9 iters of 256-thread stride over 2112 uint4)
    // stage chunk c into buffer (c&1)
    auto stage = [&](int c) {
        const uint32_t dbase = sx + (c & 1) * BUF_B;
#pragma unroll
        for (int ii = 0; ii < 9; ii++) {
            int idx = t + ii * 256;
            if (idx >= 2112) break;
            int hl = idx / 1056;
            int rr = idx - hl * 1056;
            int j = rr / 264, k = rr - j * 264;
            int iy = y0 - 1 + j;
            const bool ok = (unsigned)iy < 128u;
            int iyc = ok ? iy : 0;
            size_t slot = ((((size_t)b * 2 + wx) * 4 + c) * 256
                           + (size_t)(wy * 128 + iyc)) * 132;
            const uint4* src = ((const uint4*)g_xbf) + hl * XLO_U4 + slot * 2 + k;
            CP_ASYNC16(dbase + (uint32_t)((hl * 4 + j) * 264 + k) * 16,
                       src, ok ? 16 : 0);
        }
    };

    stage(0);
    CP_COMMIT();

#pragma unroll 1
    for (int c = 0; c < 4; c++) {
        if (c < 3) {
            stage(c + 1);
            CP_COMMIT();
            CP_WAIT(1);
        } else {
            CP_WAIT(0);
        }
        __syncthreads();

        const uint32_t sxc = sx + (c & 1) * BUF_B;
        const __nv_bfloat16* wbase = g_wB + (size_t)((w_ * 4 + c) * 9) * 2048;
#pragma unroll
        for (int ky = 0; ky < 3; ky++) {
            const int jrow = r + ky;
#pragma unroll
            for (int kx = 0; kx < 3; kx++) {
                uint32_t arow = sxc + (uint32_t)((jrow * 132 + qt * 32 + kx + lane16) * 32)
                                    + (uint32_t)(lhalf << 4);
                const uint2* bp = (const uint2*)(wbase + (size_t)(ky * 3 + kx) * 2048);
                uint32_t ah[8], al[8];
                ldmx4(ah,     arow);
                ldmx4(ah + 4, arow + 512);
                ldmx4(al,     arow + 16896);
                ldmx4(al + 4, arow + 16896 + 512);
#pragma unroll
                for (int nt = 0; nt < 8; nt++) {
                    uint2 bfh = bp[nt * 32 + lane];
                    uint2 bfl = bp[256 + nt * 32 + lane];
                    mma16816(acc[0][nt], ah,     bfh);   // hh
                    mma16816(acc[1][nt], ah + 4, bfh);
                    mma16816(acc[0][nt], al,     bfh);   // lh
                    mma16816(acc[1][nt], al + 4, bfh);
                    mma16816(acc[0][nt], ah,     bfl);   // hl
                    mma16816(acc[1][nt], ah + 4, bfl);
                }
            }
        }
        __syncthreads();   // all reads of buf (c&1) done before restage at c+2
    }

    // ---- epilogue: LN stats in-reg, smem transpose (buf0), coalesced I/O
    float* buf = (float*)smem;     // [64 co][132 px]
    const int basex = wx << 7;
#pragma unroll 1
    for (int rr = 0; rr < 2; rr++) {
        __syncthreads();
        if (r == rr) {
#pragma unroll
            for (int mt = 0; mt < 2; mt++) {
                float sa = 0.f, sb = 0.f;
#pragma unroll
                for (int nt = 0; nt < 8; nt++) {
                    sa += acc[mt][nt][0] + acc[mt][nt][1];
                    sb += acc[mt][nt][2] + acc[mt][nt][3];
                }
                sa += __shfl_xor_sync(0xffffffffu, sa, 1);
                sa += __shfl_xor_sync(0xffffffffu, sa, 2);
                sb += __shfl_xor_sync(0xffffffffu, sb, 1);
                sb += __shfl_xor_sync(0xffffffffu, sb, 2);
                const float mua = sa * (1.f / 64.f), mub = sb * (1.f / 64.f);
                float va = 0.f, vb = 0.f;
#pragma unroll
                for (int nt = 0; nt < 8; nt++) {
                    float d0 = acc[mt][nt][0] - mua, d1 = acc[mt][nt][1] - mua;
                    float d2 = acc[mt][nt][2] - mub, d3 = acc[mt][nt][3] - mub;
                    va += d0 * d0 + d1 * d1;
                    vb += d2 * d2 + d3 * d3;
                }
                va += __shfl_xor_sync(0xffffffffu, va, 1);
                va += __shfl_xor_sync(0xffffffffu, va, 2);
                vb += __shfl_xor_sync(0xffffffffu, vb, 1);
                vb += __shfl_xor_sync(0xffffffffu, vb, 2);
                const float inva = rsqrtf(va * (1.f / 64.f) + 1e-5f);
                const float invb = rsqrtf(vb * (1.f / 64.f) + 1e-5f);
                const int pxa = qt * 32 + mt * 16 + (lane >> 2);
#pragma unroll
                for (int nt = 0; nt < 8; nt++) {
                    const int co = nt * 8 + ((lane & 3) << 1);
                    buf[co * 132 + pxa]           = (acc[mt][nt][0] - mua) * inva;
                    buf[(co + 1) * 132 + pxa]     = (acc[mt][nt][1] - mua) * inva;
                    buf[co * 132 + pxa + 8]       = (acc[mt][nt][2] - mub) * invb;
                    buf[(co + 1) * 132 + pxa + 8] = (acc[mt][nt][3] - mub) * invb;
                }
            }
        }
        __syncthreads();
        {
            const int co = t >> 2, q4 = t & 3;
            const float g = lnw[co], bb_ = lnb[co];
            const int gy = wy * 128 + y0 + rr;
            const size_t gbase = (((size_t)(b * 64 + co)) * 256 + gy) * 256 + basex
                                 + q4 * 32;
            const float* bp2 = &buf[co * 132 + q4 * 32];
#pragma unroll
            for (int i = 0; i < 8; i++) {
                float4 xv = *(const float4*)(x + gbase + i * 4);
                float4 o;
                o.x = xv.x + bp2[i * 4 + 0] * g + bb_;
                o.y = xv.y + bp2[i * 4 + 1] * g + bb_;
                o.z = xv.z + bp2[i * 4 + 2] * g + bb_;
                o.w = xv.w + bp2[i * 4 + 3] * g + bb_;
                *(float4*)(out + gbase + i * 4) = o;
            }
        }
    }
}

// ===========================================================================
extern "C" void kernel_launch(void* const* d_in, const int* in_sizes, int n_in,
                              void* d_out, int out_size)
{
    const float* x      = (const float*)d_in[0];
    const float* conv_w = (const float*)d_in[1];
    const float* w_qkv  = (const float*)d_in[2];
    const float* b_qkv  = (const float*)d_in[3];
    const float* w_out  = (const float*)d_in[4];
    const float* b_out  = (const float*)d_in[5];
    const float* se_w1  = (const float*)d_in[6];
    const float* se_b1  = (const float*)d_in[7];
    const float* se_w2  = (const float*)d_in[8];
    const float* se_b2  = (const float*)d_in[9];
    const float* ln_w   = (const float*)d_in[10];
    const float* ln_b   = (const float*)d_in[11];
    float* out = (float*)d_out;

    static bool attr_set = false;
    if (!attr_set) {
        cudaFuncSetAttribute(conv_ln, cudaFuncAttributeMaxDynamicSharedMemorySize,
                             2 * BUF_B);
        attr_set = true;
    }

    prep_gen<<<16448, 288>>>(x, conv_w, w_qkv, b_qkv, w_out, b_out,
                             se_w1, se_b1, se_w2, se_b2);
    conv_ln<<<dim3(64, 4, 8), 256, 2 * BUF_B>>>(x, ln_w, ln_b, out);
}

// round 13
// speedup vs baseline: 1.2069x; 1.2069x over previous
#include <cuda_runtime.h>
#include <cuda_bf16.h>
#include <math.h>
#include <cstdint>

#define WINS 4
#define LTOK 36
#define DHD  8

// Weights, mma-B-fragment interleaved: [win][chunk4][tap9][hl2][co64][16] bf16
__device__ __align__(16) __nv_bfloat16 g_wB[4 * 4 * 9 * 2 * 64 * 16];
// X converted: [hl][b][wx2][chunk4][gy256][px132][ci16] bf16 (px slot 0 and 129+ zero)
__device__ __align__(16) __nv_bfloat16 g_xbf[2ULL * 8 * 2 * 4 * 256 * 132 * 16];

// hl=1 offset in uint4 units
#define XLO_U4 4325376ULL

__device__ __forceinline__ uint32_t smem_u32(const void* p) {
    uint32_t a;
    asm("{ .reg .u64 t; cvta.to.shared.u64 t, %1; cvt.u32.u64 %0, t; }" : "=r"(a) : "l"(p));
    return a;
}

__device__ __forceinline__ void ldmx4(uint32_t* r, uint32_t addr) {
    asm volatile("ldmatrix.sync.aligned.m8n8.x4.shared.b16 {%0,%1,%2,%3}, [%4];"
        : "=r"(r[0]), "=r"(r[1]), "=r"(r[2]), "=r"(r[3]) : "r"(addr));
}

__device__ __forceinline__ void mma16816(float* d, const uint32_t* a, uint2 b) {
    asm volatile("mma.sync.aligned.m16n8k16.row.col.f32.bf16.bf16.f32 "
        "{%0,%1,%2,%3}, {%4,%5,%6,%7}, {%8,%9}, {%0,%1,%2,%3};"
        : "+f"(d[0]), "+f"(d[1]), "+f"(d[2]), "+f"(d[3])
        : "r"(a[0]), "r"(a[1]), "r"(a[2]), "r"(a[3]), "r"(b.x), "r"(b.y));
}

#define CP_ASYNC16(dst, src, sz) \
    asm volatile("cp.async.cg.shared.global [%0], [%1], 16, %2;" \
        :: "r"(dst), "l"(src), "r"(sz) : "memory")
#define CP_COMMIT() asm volatile("cp.async.commit_group;" ::: "memory")
#define CP_WAIT(n)  asm volatile("cp.async.wait_group %0;" :: "n"(n) : "memory")

// ===========================================================================
// Kernel P: x -> bf16 hi/lo, direct (no smem). Thread = one px slot.
// Grid (256 gy, 8 = wx*4+c, 8 b), block 160 (132 active).
// ===========================================================================
__global__ void __launch_bounds__(160) prep_x(const float* __restrict__ x)
{
    const int b  = blockIdx.z;
    const int wx = blockIdx.y >> 2;
    const int c  = blockIdx.y & 3;
    const int gy = blockIdx.x;
    const int px = threadIdx.x;
    if (px >= 132) return;

    const bool in = (px >= 1 && px <= 128);
    const float* xp = x + (((size_t)(b * 64 + c * 16)) * 256 + gy) * 256
                        + wx * 128 + px - 1;
    float v[16];
#pragma unroll
    for (int ci = 0; ci < 16; ci++)
        v[ci] = in ? xp[(size_t)ci * 65536] : 0.f;

    uint32_t hw[8], lw[8];
#pragma unroll
    for (int j = 0; j < 8; j++) {
        float a = v[2 * j], bb = v[2 * j + 1];
        __nv_bfloat16 ha = __float2bfloat16(a);
        __nv_bfloat16 hb = __float2bfloat16(bb);
        __nv_bfloat16 la = __float2bfloat16(a - __bfloat162float(ha));
        __nv_bfloat16 lb = __float2bfloat16(bb - __bfloat162float(hb));
        hw[j] = (uint32_t)__bfloat16_as_ushort(ha) | ((uint32_t)__bfloat16_as_ushort(hb) << 16);
        lw[j] = (uint32_t)__bfloat16_as_ushort(la) | ((uint32_t)__bfloat16_as_ushort(lb) << 16);
    }
    const size_t slot = ((((size_t)b * 2 + wx) * 4 + c) * 256 + gy) * 132 + px;
    uint4* dh = (uint4*)g_xbf + slot * 2;
    uint4* dl = dh + XLO_U4;
    dh[0] = make_uint4(hw[0], hw[1], hw[2], hw[3]);
    dh[1] = make_uint4(hw[4], hw[5], hw[6], hw[7]);
    dl[0] = make_uint4(lw[0], lw[1], lw[2], lw[3]);
    dl[1] = make_uint4(lw[4], lw[5], lw[6], lw[7]);
}

// ===========================================================================
// Kernel A: attention + SE -> bf16 hi/lo weights in B-fragment interleave.
// ===========================================================================
__global__ void __launch_bounds__(288) gen_kernels(
    const float* __restrict__ conv_w, const float* __restrict__ w_qkv,
    const float* __restrict__ b_qkv,  const float* __restrict__ w_out,
    const float* __restrict__ b_out,  const float* __restrict__ se_w1,
    const float* __restrict__ se_b1,  const float* __restrict__ se_w2,
    const float* __restrict__ se_b2)
{
    __shared__ float sm_a[LTOK * 64];
    __shared__ float sm_qkv[LTOK * 192];
    __shared__ float sm_k1[LTOK * 64];
    __shared__ float sm_pooled[64];
    __shared__ float sm_h1[4];

    const int o = blockIdx.x;
    const int t = threadIdx.x;

    for (int idx = t; idx < LTOK * 64; idx += 288) {
        int l = idx >> 6, i = idx & 63;
        int w_ = l / 9, p = l - w_ * 9;
        sm_a[idx] = conv_w[(((w_ * 64 + o) * 64 + i) * 9) + p];
    }
    __syncthreads();

    if (t < 192) {
        float wrow[64];
#pragma unroll
        for (int i = 0; i < 64; i++) wrow[i] = w_qkv[t * 64 + i];
        const float bj = b_qkv[t];
        for (int l = 0; l < LTOK; l++) {
            float acc = bj;
#pragma unroll
            for (int i = 0; i < 64; i++) acc += sm_a[l * 64 + i] * wrow[i];
            sm_qkv[l * 192 + t] = acc;
        }
    }
    __syncthreads();

    {
        const int h = t / LTOK;
        const int l = t - h * LTOK;
        const float scale = 0.3535533905932738f;
        float sc[LTOK];
        float mx = -1e30f;
#pragma unroll
        for (int m = 0; m < LTOK; m++) {
            float s_ = 0.f;
#pragma unroll
            for (int d = 0; d < DHD; d++)
                s_ += sm_qkv[l * 192 + h * 8 + d] * sm_qkv[m * 192 + 64 + h * 8 + d];
            sc[m] = s_ * scale;
            mx = fmaxf(mx, sc[m]);
        }
        float denom = 0.f;
#pragma unroll
        for (int m = 0; m < LTOK; m++) { sc[m] = expf(sc[m] - mx); denom += sc[m]; }
        const float inv = 1.f / denom;
        float ov[DHD];
#pragma unroll
        for (int d = 0; d < DHD; d++) ov[d] = 0.f;
#pragma unroll
        for (int m = 0; m < LTOK; m++) {
            const float p_ = sc[m];
#pragma unroll
            for (int d = 0; d < DHD; d++)
                ov[d] += p_ * sm_qkv[m * 192 + 128 + h * 8 + d];
        }
#pragma unroll
        for (int d = 0; d < DHD; d++)
            sm_a[l * 64 + h * 8 + d] = ov[d] * inv;
    }
    __syncthreads();

    if (t < 64) {
        const float bj = b_out[t];
        for (int l = 0; l < LTOK; l++) {
            float acc = bj;
#pragma unroll
            for (int c = 0; c < 64; c++) acc += sm_a[l * 64 + c] * w_out[t * 64 + c];
            sm_k1[l * 64 + t] = acc;
        }
    }
    __syncthreads();

    for (int w_ = 0; w_ < WINS; w_++) {
        if (t < 64) {
            float pl = 0.f;
#pragma unroll
            for (int p = 0; p < 9; p++) pl += sm_k1[(w_ * 9 + p) * 64 + t];
            sm_pooled[t] = pl * (1.f / 9.f);
        }
        __syncthreads();
        if (t < 4) {
            float a = se_b1[w_ * 4 + t];
            for (int i = 0; i < 64; i++)
                a += sm_pooled[i] * se_w1[(w_ * 4 + t) * 64 + i];
            sm_h1[t] = fmaxf(a, 0.f);
        }
        __syncthreads();
        if (t < 64) {   // t = ci (global)
            float z = se_b2[w_ * 64 + t];
#pragma unroll
            for (int r = 0; r < 4; r++) z += sm_h1[r] * se_w2[(w_ * 64 + t) * 4 + r];
            const float s_ = 1.f / (1.f + expf(-z));
            const int chunk = t >> 4, k = t & 15;
            const int j = (k & 7) >> 1;
            const int pos = 4 * j + (k & 1) + ((k >> 3) << 1);
#pragma unroll
            for (int p = 0; p < 9; p++) {
                float vv = sm_k1[(w_ * 9 + p) * 64 + t] * s_;
                __nv_bfloat16 h = __float2bfloat16(vv);
                __nv_bfloat16 l = __float2bfloat16(vv - __bfloat162float(h));
                size_t base = ((size_t)((w_ * 4 + chunk) * 9 + p) * 2) * 1024
                              + (size_t)o * 16 + pos;
                g_wB[base] = h;           // hl = 0
                g_wB[base + 1024] = l;    // hl = 1
            }
        }
        __syncthreads();
    }
}

// ===========================================================================
// Kernel B: mma.sync implicit-GEMM conv + LN + residual.
// cp.async double-buffered X staging; B fragments loaded once per (tap, nt).
// ===========================================================================
#define BUF_B 33792

__global__ void __launch_bounds__(256, 2) conv_ln(
    const float* __restrict__ x,
    const float* __restrict__ ln_w,
    const float* __restrict__ ln_b,
    float* __restrict__ out)
{
    extern __shared__ __align__(16) char smem[];   // 2 x 33792
    __shared__ float lnw[64], lnb[64];

    const int b  = blockIdx.z;
    const int w_ = blockIdx.y;
    const int wy = w_ >> 1, wx = w_ & 1;
    const int y0 = blockIdx.x << 1;
    const int t  = threadIdx.x;
    const int wid = t >> 5, lane = t & 31;
    const int r  = wid >> 2, qt = wid & 3;

    if (t < 64) { lnw[t] = ln_w[t]; lnb[t] = ln_b[t]; }

    float acc[2][8][4];
#pragma unroll
    for (int mt = 0; mt < 2; mt++)
#pragma unroll
        for (int nt = 0; nt < 8; nt++)
#pragma unroll
            for (int i = 0; i < 4; i++) acc[mt][nt][i] = 0.f;

    const uint32_t sx = smem_u32(smem);
    const int lane16 = lane & 15, lhalf = lane >> 4;

    auto stage = [&](int c) {
        const uint32_t dbase = sx + (c & 1) * BUF_B;
#pragma unroll
        for (int ii = 0; ii < 9; ii++) {
            int idx = t + ii * 256;
            if (idx >= 2112) break;
            int hl = idx / 1056;
            int rr = idx - hl * 1056;
            int j = rr / 264, k = rr - j * 264;
            int iy = y0 - 1 + j;
            const bool ok = (unsigned)iy < 128u;
            int iyc = ok ? iy : 0;
            size_t slot = ((((size_t)b * 2 + wx) * 4 + c) * 256
                           + (size_t)(wy * 128 + iyc)) * 132;
            const uint4* src = ((const uint4*)g_xbf) + hl * XLO_U4 + slot * 2 + k;
            CP_ASYNC16(dbase + (uint32_t)((hl * 4 + j) * 264 + k) * 16,
                       src, ok ? 16 : 0);
        }
    };

    stage(0);
    CP_COMMIT();

#pragma unroll 1
    for (int c = 0; c < 4; c++) {
        if (c < 3) {
            stage(c + 1);
            CP_COMMIT();
            CP_WAIT(1);
        } else {
            CP_WAIT(0);
        }
        __syncthreads();

        const uint32_t sxc = sx + (c & 1) * BUF_B;
        const __nv_bfloat16* wbase = g_wB + (size_t)((w_ * 4 + c) * 9) * 2048;
#pragma unroll
        for (int ky = 0; ky < 3; ky++) {
            const int jrow = r + ky;
#pragma unroll
            for (int kx = 0; kx < 3; kx++) {
                uint32_t arow = sxc + (uint32_t)((jrow * 132 + qt * 32 + kx + lane16) * 32)
                                    + (uint32_t)(lhalf << 4);
                const uint2* bp = (const uint2*)(wbase + (size_t)(ky * 3 + kx) * 2048);
                uint32_t ah[8], al[8];
                ldmx4(ah,     arow);
                ldmx4(ah + 4, arow + 512);
                ldmx4(al,     arow + 16896);
                ldmx4(al + 4, arow + 16896 + 512);
#pragma unroll
                for (int nt = 0; nt < 8; nt++) {
                    uint2 bfh = bp[nt * 32 + lane];
                    uint2 bfl = bp[256 + nt * 32 + lane];
                    mma16816(acc[0][nt], ah,     bfh);   // hh
                    mma16816(acc[1][nt], ah + 4, bfh);
                    mma16816(acc[0][nt], al,     bfh);   // lh
                    mma16816(acc[1][nt], al + 4, bfh);
                    mma16816(acc[0][nt], ah,     bfl);   // hl
                    mma16816(acc[1][nt], ah + 4, bfl);
                }
            }
        }
        __syncthreads();   // all reads of buf (c&1) done before restage at c+2
    }

    // ---- epilogue: LN stats in-reg, smem transpose (buf0), coalesced I/O
    float* buf = (float*)smem;     // [64 co][132 px]
    const int basex = wx << 7;
#pragma unroll 1
    for (int rr = 0; rr < 2; rr++) {
        __syncthreads();
        if (r == rr) {
#pragma unroll
            for (int mt = 0; mt < 2; mt++) {
                float sa = 0.f, sb = 0.f;
#pragma unroll
                for (int nt = 0; nt < 8; nt++) {
                    sa += acc[mt][nt][0] + acc[mt][nt][1];
                    sb += acc[mt][nt][2] + acc[mt][nt][3];
                }
                sa += __shfl_xor_sync(0xffffffffu, sa, 1);
                sa += __shfl_xor_sync(0xffffffffu, sa, 2);
                sb += __shfl_xor_sync(0xffffffffu, sb, 1);
                sb += __shfl_xor_sync(0xffffffffu, sb, 2);
                const float mua = sa * (1.f / 64.f), mub = sb * (1.f / 64.f);
                float va = 0.f, vb = 0.f;
#pragma unroll
                for (int nt = 0; nt < 8; nt++) {
                    float d0 = acc[mt][nt][0] - mua, d1 = acc[mt][nt][1] - mua;
                    float d2 = acc[mt][nt][2] - mub, d3 = acc[mt][nt][3] - mub;
                    va += d0 * d0 + d1 * d1;
                    vb += d2 * d2 + d3 * d3;
                }
                va += __shfl_xor_sync(0xffffffffu, va, 1);
                va += __shfl_xor_sync(0xffffffffu, va, 2);
                vb += __shfl_xor_sync(0xffffffffu, vb, 1);
                vb += __shfl_xor_sync(0xffffffffu, vb, 2);
                const float inva = rsqrtf(va * (1.f / 64.f) + 1e-5f);
                const float invb = rsqrtf(vb * (1.f / 64.f) + 1e-5f);
                const int pxa = qt * 32 + mt * 16 + (lane >> 2);
#pragma unroll
                for (int nt = 0; nt < 8; nt++) {
                    const int co = nt * 8 + ((lane & 3) << 1);
                    buf[co * 132 + pxa]           = (acc[mt][nt][0] - mua) * inva;
                    buf[(co + 1) * 132 + pxa]     = (acc[mt][nt][1] - mua) * inva;
                    buf[co * 132 + pxa + 8]       = (acc[mt][nt][2] - mub) * invb;
                    buf[(co + 1) * 132 + pxa + 8] = (acc[mt][nt][3] - mub) * invb;
                }
            }
        }
        __syncthreads();
        {
            const int co = t >> 2, q4 = t & 3;
            const float g = lnw[co], bb_ = lnb[co];
            const int gy = wy * 128 + y0 + rr;
            const size_t gbase = (((size_t)(b * 64 + co)) * 256 + gy) * 256 + basex
                                 + q4 * 32;
            const float* bp2 = &buf[co * 132 + q4 * 32];
#pragma unroll
            for (int i = 0; i < 8; i++) {
                float4 xv = *(const float4*)(x + gbase + i * 4);
                float4 o;
                o.x = xv.x + bp2[i * 4 + 0] * g + bb_;
                o.y = xv.y + bp2[i * 4 + 1] * g + bb_;
                o.z = xv.z + bp2[i * 4 + 2] * g + bb_;
                o.w = xv.w + bp2[i * 4 + 3] * g + bb_;
                *(float4*)(out + gbase + i * 4) = o;
            }
        }
    }
}

// ===========================================================================
extern "C" void kernel_launch(void* const* d_in, const int* in_sizes, int n_in,
                              void* d_out, int out_size)
{
    const float* x      = (const float*)d_in[0];
    const float* conv_w = (const float*)d_in[1];
    const float* w_qkv  = (const float*)d_in[2];
    const float* b_qkv  = (const float*)d_in[3];
    const float* w_out  = (const float*)d_in[4];
    const float* b_out  = (const float*)d_in[5];
    const float* se_w1  = (const float*)d_in[6];
    const float* se_b1  = (const float*)d_in[7];
    const float* se_w2  = (const float*)d_in[8];
    const float* se_b2  = (const float*)d_in[9];
    const float* ln_w   = (const float*)d_in[10];
    const float* ln_b   = (const float*)d_in[11];
    float* out = (float*)d_out;

    static bool attr_set = false;
    if (!attr_set) {
        cudaFuncSetAttribute(conv_ln, cudaFuncAttributeMaxDynamicSharedMemorySize,
                             2 * BUF_B);
        attr_set = true;
    }

    prep_x<<<dim3(256, 8, 8), 160>>>(x);
    gen_kernels<<<64, 288>>>(conv_w, w_qkv, b_qkv, w_out, b_out,
                             se_w1, se_b1, se_w2, se_b2);
    conv_ln<<<dim3(64, 4, 8), 256, 2 * BUF_B>>>(x, ln_w, ln_b, out);
}